// round 3
// baseline (speedup 1.0000x reference)
#include <cuda_runtime.h>
#include <math.h>

#define THREADS 256
#define RPT 8          // rows per thread (4 packed pairs)
#define KC 32          // codebook size
#define DD 8           // codebook dim

__device__ double g_sum;
__device__ unsigned int g_counts[KC];

static __device__ __forceinline__ unsigned long long pk2(float lo, float hi) {
    unsigned long long r;
    asm("mov.b64 %0, {%1,%2};" : "=l"(r) : "f"(lo), "f"(hi));
    return r;
}
static __device__ __forceinline__ void upk2(unsigned long long v, float& lo, float& hi) {
    asm("mov.b64 {%0,%1}, %2;" : "=f"(lo), "=f"(hi) : "l"(v));
}
// packed f32x2 fma: d.lo = a.lo*b.lo + c.lo ; d.hi = a.hi*b.hi + c.hi
static __device__ __forceinline__ unsigned long long ffma2(unsigned long long a,
                                                           unsigned long long b,
                                                           unsigned long long c) {
    unsigned long long r;
    asm("fma.rn.f32x2 %0, %1, %2, %3;" : "=l"(r) : "l"(a), "l"(b), "l"(c));
    return r;
}

__global__ void vq_init() {
    if (threadIdx.x == 0) g_sum = 0.0;
    if (threadIdx.x < KC) g_counts[threadIdx.x] = 0u;
}

__global__ __launch_bounds__(THREADS) void vq_main(
    const float* __restrict__ z, const float* __restrict__ cb,
    float* __restrict__ out, int nrows)
{
    __shared__ unsigned long long s_cdup[KC][DD];   // codebook element duplicated (c,c)
    __shared__ unsigned long long s_cn[KC];         // ||c||^2 duplicated
    __shared__ float s_craw[KC][DD + 1];            // padded (stride 9) -> conflict-free gather
    __shared__ unsigned int s_cnt[KC];
    __shared__ double s_red[THREADS / 32];

    const int tid = threadIdx.x;

    if (tid < KC) {
        float cn = 0.f;
#pragma unroll
        for (int d = 0; d < DD; d++) {
            float v = cb[tid * DD + d];
            s_cdup[tid][d] = pk2(v, v);
            s_craw[tid][d] = v;
            cn = fmaf(v, v, cn);
        }
        s_cn[tid] = pk2(cn, cn);
        s_cnt[tid] = 0u;
    }
    __syncthreads();

    const long long base = (long long)blockIdx.x * (THREADS * RPT) + tid;

    // ---- load 8 rows, pack two rows per 64-bit lane pair ----
    unsigned long long zp[RPT / 2][DD];
    bool valid[RPT];
#pragma unroll
    for (int p = 0; p < RPT / 2; ++p) {
        long long ra = base + (long long)(2 * p) * THREADS;
        long long rb = ra + THREADS;
        valid[2 * p]     = (ra < nrows);
        valid[2 * p + 1] = (rb < nrows);
        long long la = valid[2 * p] ? ra : 0;
        long long lb = valid[2 * p + 1] ? rb : 0;
        float4 a0 = *(const float4*)(z + la * DD);
        float4 a1 = *(const float4*)(z + la * DD + 4);
        float4 b0 = *(const float4*)(z + lb * DD);
        float4 b1 = *(const float4*)(z + lb * DD + 4);
        zp[p][0] = pk2(a0.x, b0.x); zp[p][1] = pk2(a0.y, b0.y);
        zp[p][2] = pk2(a0.z, b0.z); zp[p][3] = pk2(a0.w, b0.w);
        zp[p][4] = pk2(a1.x, b1.x); zp[p][5] = pk2(a1.y, b1.y);
        zp[p][6] = pk2(a1.z, b1.z); zp[p][7] = pk2(a1.w, b1.w);
    }

    float best[RPT];
    int   bi[RPT];
#pragma unroll
    for (int i = 0; i < RPT; i++) { best[i] = 3.4e38f; bi[i] = 0; }

    const unsigned long long NEG2 = pk2(-2.f, -2.f);

    // ---- argmin over 32 codes: dist = ||c||^2 - 2 z.c  (same ordering as reference) ----
#pragma unroll 4
    for (int k = 0; k < KC; k++) {
        unsigned long long c0 = s_cdup[k][0], c1 = s_cdup[k][1],
                           c2 = s_cdup[k][2], c3 = s_cdup[k][3],
                           c4 = s_cdup[k][4], c5 = s_cdup[k][5],
                           c6 = s_cdup[k][6], c7 = s_cdup[k][7];
        unsigned long long cnp = s_cn[k];
#pragma unroll
        for (int p = 0; p < RPT / 2; p++) {
            unsigned long long acc = ffma2(zp[p][0], c0, 0ULL);
            acc = ffma2(zp[p][1], c1, acc);
            acc = ffma2(zp[p][2], c2, acc);
            acc = ffma2(zp[p][3], c3, acc);
            acc = ffma2(zp[p][4], c4, acc);
            acc = ffma2(zp[p][5], c5, acc);
            acc = ffma2(zp[p][6], c6, acc);
            acc = ffma2(zp[p][7], c7, acc);
            unsigned long long dist = ffma2(acc, NEG2, cnp);
            float da, db;
            upk2(dist, da, db);
            if (da < best[2 * p])     { best[2 * p] = da;     bi[2 * p] = k; }
            if (db < best[2 * p + 1]) { best[2 * p + 1] = db; bi[2 * p + 1] = k; }
        }
    }

    // ---- epilogue: gather code, compute st = z + (zq - z), loss, histogram, store ----
    float lsum = 0.f;
#pragma unroll
    for (int p = 0; p < RPT / 2; p++) {
        const int ba = bi[2 * p], bb = bi[2 * p + 1];
        float oa[DD], ob[DD];
        float sa = 0.f, sb = 0.f;
#pragma unroll
        for (int d = 0; d < DD; d++) {
            float zlo, zhi;
            upk2(zp[p][d], zlo, zhi);
            float ca = s_craw[ba][d];
            float cbv = s_craw[bb][d];
            float da = ca - zlo;
            float db = cbv - zhi;
            oa[d] = zlo + da;     // z + (z_q - z), matches reference FP order
            ob[d] = zhi + db;
            sa = fmaf(da, da, sa);
            sb = fmaf(db, db, sb);
        }
        long long ra = base + (long long)(2 * p) * THREADS;
        if (valid[2 * p]) {
            lsum += sa;
            *(float4*)(out + ra * DD)     = make_float4(oa[0], oa[1], oa[2], oa[3]);
            *(float4*)(out + ra * DD + 4) = make_float4(oa[4], oa[5], oa[6], oa[7]);
            atomicAdd(&s_cnt[ba], 1u);
        }
        if (valid[2 * p + 1]) {
            long long rb = ra + THREADS;
            lsum += sb;
            *(float4*)(out + rb * DD)     = make_float4(ob[0], ob[1], ob[2], ob[3]);
            *(float4*)(out + rb * DD + 4) = make_float4(ob[4], ob[5], ob[6], ob[7]);
            atomicAdd(&s_cnt[bb], 1u);
        }
    }

    // ---- block reductions ----
#pragma unroll
    for (int off = 16; off; off >>= 1)
        lsum += __shfl_down_sync(0xffffffffu, lsum, off);
    if ((tid & 31) == 0) s_red[tid >> 5] = (double)lsum;
    __syncthreads();
    if (tid == 0) {
        double t = 0.0;
#pragma unroll
        for (int w = 0; w < THREADS / 32; w++) t += s_red[w];
        atomicAdd(&g_sum, t);
    }
    if (tid < KC) {
        unsigned int c = s_cnt[tid];
        if (c) atomicAdd(&g_counts[tid], c);
    }
}

__global__ void vq_fin(float* __restrict__ out, long long ndelem, int nrows, int write_scalars) {
    int t = threadIdx.x;  // 32 threads
    double p = (double)g_counts[t] / (double)nrows;
    double term = p * log(p + 1e-10);
#pragma unroll
    for (int off = 16; off; off >>= 1)
        term += __shfl_down_sync(0xffffffffu, term, off);
    if (t == 0 && write_scalars) {
        out[ndelem]     = (float)((g_sum * 1.25) / (double)ndelem);
        out[ndelem + 1] = (float)exp(-term);
    }
}

extern "C" void kernel_launch(void* const* d_in, const int* in_sizes, int n_in,
                              void* d_out, int out_size) {
    const float* z  = (const float*)d_in[0];
    const float* cb = (const float*)d_in[1];
    float* out = (float*)d_out;

    int nrows = in_sizes[0] / DD;
    long long ndelem = (long long)nrows * DD;
    int blocks = (nrows + THREADS * RPT - 1) / (THREADS * RPT);
    int write_scalars = ((long long)out_size >= ndelem + 2) ? 1 : 0;

    vq_init<<<1, 32>>>();
    vq_main<<<blocks, THREADS>>>(z, cb, out, nrows);
    vq_fin<<<1, 32>>>(out, ndelem, nrows, write_scalars);
}

// round 5
// speedup vs baseline: 1.1271x; 1.1271x over previous
#include <cuda_runtime.h>
#include <math.h>

#define THREADS 256
#define RPT 4          // rows per thread (2 packed pairs) -> MLP_p1 = 8 LDG.128
#define KC 32          // codebook size
#define DD 8           // codebook dim

__device__ double g_sum;                 // zero-init at load; reset by last block each run
__device__ unsigned int g_counts[KC];
__device__ unsigned int g_done;

static __device__ __forceinline__ unsigned long long pk2(float lo, float hi) {
    unsigned long long r;
    asm("mov.b64 %0, {%1,%2};" : "=l"(r) : "f"(lo), "f"(hi));
    return r;
}
static __device__ __forceinline__ void upk2(unsigned long long v, float& lo, float& hi) {
    asm("mov.b64 {%0,%1}, %2;" : "=f"(lo), "=f"(hi) : "l"(v));
}
// packed f32x2 fma: d.lo = a.lo*b.lo + c.lo ; d.hi = a.hi*b.hi + c.hi
static __device__ __forceinline__ unsigned long long ffma2(unsigned long long a,
                                                           unsigned long long b,
                                                           unsigned long long c) {
    unsigned long long r;
    asm("fma.rn.f32x2 %0, %1, %2, %3;" : "=l"(r) : "l"(a), "l"(b), "l"(c));
    return r;
}

__global__ __launch_bounds__(THREADS) void vq_fused(
    const float* __restrict__ z, const float* __restrict__ cb,
    float* __restrict__ out, int nrows, long long ndelem, int write_scalars)
{
    __shared__ unsigned long long s_cdup[KC][DD];   // codebook element duplicated (c,c)
    __shared__ unsigned long long s_cn[KC];         // ||c||^2 duplicated
    __shared__ float s_craw[KC][DD + 1];            // padded (stride 9) -> conflict-free gather
    __shared__ unsigned int s_cnt[KC];
    __shared__ double s_red[THREADS / 32];
    __shared__ int s_islast;

    const int tid = threadIdx.x;

    if (tid < KC) {
        float cn = 0.f;
#pragma unroll
        for (int d = 0; d < DD; d++) {
            float v = cb[tid * DD + d];
            s_cdup[tid][d] = pk2(v, v);
            s_craw[tid][d] = v;
            cn = fmaf(v, v, cn);
        }
        s_cn[tid] = pk2(cn, cn);
        s_cnt[tid] = 0u;
    }
    __syncthreads();

    const long long base = (long long)blockIdx.x * (THREADS * RPT) + tid;

    // ---- load 4 rows, pack two rows per 64-bit lane pair (8 LDG.128 front batch) ----
    unsigned long long zp[RPT / 2][DD];
    bool valid[RPT];
#pragma unroll
    for (int p = 0; p < RPT / 2; ++p) {
        long long ra = base + (long long)(2 * p) * THREADS;
        long long rb = ra + THREADS;
        valid[2 * p]     = (ra < nrows);
        valid[2 * p + 1] = (rb < nrows);
        long long la = valid[2 * p] ? ra : 0;
        long long lb = valid[2 * p + 1] ? rb : 0;
        float4 a0 = __ldcs((const float4*)(z + la * DD));
        float4 a1 = __ldcs((const float4*)(z + la * DD + 4));
        float4 b0 = __ldcs((const float4*)(z + lb * DD));
        float4 b1 = __ldcs((const float4*)(z + lb * DD + 4));
        zp[p][0] = pk2(a0.x, b0.x); zp[p][1] = pk2(a0.y, b0.y);
        zp[p][2] = pk2(a0.z, b0.z); zp[p][3] = pk2(a0.w, b0.w);
        zp[p][4] = pk2(a1.x, b1.x); zp[p][5] = pk2(a1.y, b1.y);
        zp[p][6] = pk2(a1.z, b1.z); zp[p][7] = pk2(a1.w, b1.w);
    }

    float best[RPT];
    int   bi[RPT];
#pragma unroll
    for (int i = 0; i < RPT; i++) { best[i] = 3.4e38f; bi[i] = 0; }

    const unsigned long long NEG2 = pk2(-2.f, -2.f);

    // ---- argmin over 32 codes: dist = ||c||^2 - 2 z.c (argmin matches reference) ----
#pragma unroll 4
    for (int k = 0; k < KC; k++) {
        unsigned long long c0 = s_cdup[k][0], c1 = s_cdup[k][1],
                           c2 = s_cdup[k][2], c3 = s_cdup[k][3],
                           c4 = s_cdup[k][4], c5 = s_cdup[k][5],
                           c6 = s_cdup[k][6], c7 = s_cdup[k][7];
        unsigned long long cnp = s_cn[k];
#pragma unroll
        for (int p = 0; p < RPT / 2; p++) {
            unsigned long long acc = ffma2(zp[p][0], c0, 0ULL);
            acc = ffma2(zp[p][1], c1, acc);
            acc = ffma2(zp[p][2], c2, acc);
            acc = ffma2(zp[p][3], c3, acc);
            acc = ffma2(zp[p][4], c4, acc);
            acc = ffma2(zp[p][5], c5, acc);
            acc = ffma2(zp[p][6], c6, acc);
            acc = ffma2(zp[p][7], c7, acc);
            unsigned long long dist = ffma2(acc, NEG2, cnp);
            float da, db;
            upk2(dist, da, db);
            if (da < best[2 * p])     { best[2 * p] = da;     bi[2 * p] = k; }
            if (db < best[2 * p + 1]) { best[2 * p + 1] = db; bi[2 * p + 1] = k; }
        }
    }

    // ---- epilogue: gather code, st = z + (zq - z), loss, histogram, store ----
    float lsum = 0.f;
#pragma unroll
    for (int p = 0; p < RPT / 2; p++) {
        const int ba = bi[2 * p], bb = bi[2 * p + 1];
        float oa[DD], ob[DD];
        float sa = 0.f, sb = 0.f;
#pragma unroll
        for (int d = 0; d < DD; d++) {
            float zlo, zhi;
            upk2(zp[p][d], zlo, zhi);
            float ca  = s_craw[ba][d];
            float cbv = s_craw[bb][d];
            float da = ca - zlo;
            float db = cbv - zhi;
            oa[d] = zlo + da;     // z + (z_q - z), matches reference FP order
            ob[d] = zhi + db;
            sa = fmaf(da, da, sa);
            sb = fmaf(db, db, sb);
        }
        long long ra = base + (long long)(2 * p) * THREADS;
        if (valid[2 * p]) {
            lsum += sa;
            __stcs((float4*)(out + ra * DD),     make_float4(oa[0], oa[1], oa[2], oa[3]));
            __stcs((float4*)(out + ra * DD + 4), make_float4(oa[4], oa[5], oa[6], oa[7]));
            atomicAdd(&s_cnt[ba], 1u);
        }
        if (valid[2 * p + 1]) {
            long long rb = ra + THREADS;
            lsum += sb;
            __stcs((float4*)(out + rb * DD),     make_float4(ob[0], ob[1], ob[2], ob[3]));
            __stcs((float4*)(out + rb * DD + 4), make_float4(ob[4], ob[5], ob[6], ob[7]));
            atomicAdd(&s_cnt[bb], 1u);
        }
    }

    // ---- block reductions -> global accumulators ----
#pragma unroll
    for (int off = 16; off; off >>= 1)
        lsum += __shfl_down_sync(0xffffffffu, lsum, off);
    if ((tid & 31) == 0) s_red[tid >> 5] = (double)lsum;
    __syncthreads();
    if (tid == 0) {
        double t = 0.0;
#pragma unroll
        for (int w = 0; w < THREADS / 32; w++) t += s_red[w];
        atomicAdd(&g_sum, t);
    }
    if (tid < KC) {
        unsigned int c = s_cnt[tid];
        if (c) atomicAdd(&g_counts[tid], c);
    }

    // ---- last-block finalize (threadfence + ticket pattern) ----
    __syncthreads();                 // block-scope: all atomics above are issued
    if (tid == 0) {
        __threadfence();             // make this block's contributions device-visible
        unsigned int ticket = atomicAdd(&g_done, 1u);
        s_islast = (ticket == gridDim.x - 1) ? 1 : 0;
    }
    __syncthreads();

    if (s_islast && tid < 32) {
        unsigned int cnt = g_counts[tid];
        double p = (double)cnt / (double)nrows;
        double term = p * log(p + 1e-10);
#pragma unroll
        for (int off = 16; off; off >>= 1)
            term += __shfl_down_sync(0xffffffffu, term, off);
        if (tid == 0) {
            double s = atomicAdd(&g_sum, 0.0);   // atomic read
            if (write_scalars) {
                out[ndelem]     = (float)((s * 1.25) / (double)ndelem);
                out[ndelem + 1] = (float)exp(-term);
            }
            g_sum = 0.0;                          // reset for next graph replay
        }
        g_counts[tid] = 0u;
        __threadfence();
        if (tid == 0) g_done = 0u;
    }
}

extern "C" void kernel_launch(void* const* d_in, const int* in_sizes, int n_in,
                              void* d_out, int out_size) {
    const float* z  = (const float*)d_in[0];
    const float* cb = (const float*)d_in[1];
    float* out = (float*)d_out;

    int nrows = in_sizes[0] / DD;
    long long ndelem = (long long)nrows * DD;
    int blocks = (nrows + THREADS * RPT - 1) / (THREADS * RPT);
    int write_scalars = ((long long)out_size >= ndelem + 2) ? 1 : 0;

    vq_fused<<<blocks, THREADS>>>(z, cb, out, nrows, ndelem, write_scalars);
}